// round 13
// baseline (speedup 1.0000x reference)
#include <cuda_runtime.h>
#include <cuda_fp16.h>
#include <math.h>
#include <stdint.h>

// ---------------- problem constants ----------------
#define NN   50000
#define EE   1600000
#define GG   64

// ---------------- device scratch (no allocation allowed) ----------------
__device__ float g_h0[(size_t)NN * 128];
__device__ float g_h1[(size_t)NN * 128];
__device__ float g_hf[(size_t)NN * 128];
__device__ float g_dinv[NN];
__device__ int   g_deg[NN];
__device__ int   g_off[NN + 1];
__device__ int   g_cur[NN];
__device__ int   g_srcv[EE + NN];
__device__ int   g_bsum[256];
__device__ int   g_boff[256];
__device__ __half g_bhe[128 * 1024];          // embed B hi fp16 [n][k]
__device__ __half g_ble[128 * 1024];          // embed B lo fp16
__device__ __half g_bhm[3 * 128 * 2048];      // mp B hi fp16 x3
__device__ __half g_blm[3 * 128 * 2048];      // mp B lo fp16 x3
__device__ float g_wtr[2048 * 32];            // readout [k][o] fp32
__device__ float g_sums[GG * 128];
__device__ float g_cnts[GG];

// ---------------- helpers ----------------
__device__ __forceinline__ uint32_t smem_to_u32(const void* p) {
    uint32_t a;
    asm("{ .reg .u64 t; cvta.to.shared.u64 t, %1; cvt.u32.u64 %0, t; }" : "=r"(a) : "l"(p));
    return a;
}
#define SWZ(x) ((x) ^ (((x) >> 3) & 0x70))

#define LDSM4(R, addr)                                                           \
    asm volatile("ldmatrix.sync.aligned.m8n8.x4.shared.b16 {%0,%1,%2,%3}, [%4];" \
                 : "=r"((R)[0]), "=r"((R)[1]), "=r"((R)[2]), "=r"((R)[3])        \
                 : "r"(addr))
#define LDSM2(R, addr)                                                           \
    asm volatile("ldmatrix.sync.aligned.m8n8.x2.shared.b16 {%0,%1}, [%2];"       \
                 : "=r"((R)[0]), "=r"((R)[1]) : "r"(addr))
// fp16 inputs, fp32 accumulator (main term)
#define MMA_F32(D, A, B)                                                         \
    asm volatile("mma.sync.aligned.m16n8k16.row.col.f32.f16.f16.f32 "            \
                 "{%0,%1,%2,%3}, {%4,%5,%6,%7}, {%8,%9}, {%0,%1,%2,%3};"         \
                 : "+f"((D)[0]), "+f"((D)[1]), "+f"((D)[2]), "+f"((D)[3])        \
                 : "r"((A)[0]), "r"((A)[1]), "r"((A)[2]), "r"((A)[3]),           \
                   "r"((B)[0]), "r"((B)[1]))
// fp16 inputs, fp16 accumulator (small correction terms)
#define MMA_F16(D, A, B)                                                         \
    asm volatile("mma.sync.aligned.m16n8k16.row.col.f16.f16.f16.f16 "            \
                 "{%0,%1}, {%2,%3,%4,%5}, {%6,%7}, {%0,%1};"                     \
                 : "+r"((D)[0]), "+r"((D)[1])                                    \
                 : "r"((A)[0]), "r"((A)[1]), "r"((A)[2]), "r"((A)[3]),           \
                   "r"((B)[0]), "r"((B)[1]))
#define CP_ASYNC16(sa, gp)                                                       \
    asm volatile("cp.async.ca.shared.global [%0], [%1], 16;" :: "r"(sa), "l"(gp))
#define CP_COMMIT() asm volatile("cp.async.commit_group;" ::: "memory")
#define CP_WAIT1()  asm volatile("cp.async.wait_group 1;" ::: "memory")

// ---------------- prep kernels ----------------
__global__ void count_deg(const int* __restrict__ ecol, int* __restrict__ deg) {
    int e = blockIdx.x * blockDim.x + threadIdx.x;
    if (e < EE) atomicAdd(&deg[ecol[e]], 1);
}

__global__ void deg_bsum(const int* __restrict__ deg, int* __restrict__ bsum,
                         float* __restrict__ dinv) {
    __shared__ int sh[256];
    int t = threadIdx.x;
    int i = blockIdx.x * 256 + t;
    int d = (i < NN) ? deg[i] + 1 : 0;
    if (i < NN) dinv[i] = rsqrtf((float)d);
    sh[t] = d;
    __syncthreads();
    for (int s = 128; s > 0; s >>= 1) {
        if (t < s) sh[t] += sh[t + s];
        __syncthreads();
    }
    if (t == 0) bsum[blockIdx.x] = sh[0];
}
__global__ void scan_bsum(const int* __restrict__ bsum, int* __restrict__ boff,
                          int nb, int* __restrict__ off) {
    __shared__ int sh[256];
    int t = threadIdx.x;
    int v = (t < nb) ? bsum[t] : 0;
    sh[t] = v;
    __syncthreads();
    for (int d = 1; d < 256; d <<= 1) {
        int u = (t >= d) ? sh[t - d] : 0;
        __syncthreads();
        sh[t] += u;
        __syncthreads();
    }
    if (t < nb) boff[t] = sh[t] - v;
    if (t == 0) off[NN] = EE + NN;
}
__global__ void scan_write(const int* __restrict__ deg, const int* __restrict__ boff,
                           int* __restrict__ off, int* __restrict__ cur) {
    __shared__ int sh[256];
    int t = threadIdx.x;
    int i = blockIdx.x * 256 + t;
    int v = (i < NN) ? deg[i] + 1 : 0;
    sh[t] = v;
    __syncthreads();
    for (int d = 1; d < 256; d <<= 1) {
        int u = (t >= d) ? sh[t - d] : 0;
        __syncthreads();
        sh[t] += u;
        __syncthreads();
    }
    if (i < NN) {
        int o = boff[blockIdx.x] + sh[t] - v;
        off[i] = o;
        cur[i] = o;
    }
}
__global__ void fill_csr(const int* __restrict__ erow, const int* __restrict__ ecol,
                         int* __restrict__ cur, int* __restrict__ srcv) {
    int e = blockIdx.x * blockDim.x + threadIdx.x;
    if (e >= EE + NN) return;
    int r, c;
    if (e < EE) { r = erow[e]; c = ecol[e]; }
    else        { r = c = e - EE; }
    int p = atomicAdd(&cur[c], 1);
    srcv[p] = r;
}

// W[2][out=128][in][8] -> B[n][k] fp16 hi/lo, k = i*16 + t*8 + h
__global__ void make_b_embed(const float* __restrict__ W, __half* __restrict__ bhi,
                             __half* __restrict__ blo,
                             int* __restrict__ deg, float* __restrict__ sums,
                             float* __restrict__ cnts) {
    const int in_dim = 64;
    int idx = blockIdx.x * blockDim.x + threadIdx.x;
    if (idx < NN) deg[idx] = 0;
    if (idx < GG * 128) sums[idx] = 0.0f;
    if (idx < GG) cnts[idx] = 0.0f;
    int K = in_dim * 16;
    if (idx >= 128 * K) return;
    int n = idx / K;
    int k = idx % K;
    int h = k & 7, t = (k >> 3) & 1, i = k >> 4;
    float w = W[(((size_t)t * 128 + n) * in_dim + i) * 8 + h];
    __half hi = __float2half_rn(w);
    __half lo = __float2half_rn(w - __half2float(hi));
    bhi[idx] = hi;
    blo[idx] = lo;
}
__global__ void make_b(const float* __restrict__ W, __half* __restrict__ bhi,
                       __half* __restrict__ blo, int in_dim) {
    int idx = blockIdx.x * blockDim.x + threadIdx.x;
    int K = in_dim * 16;
    if (idx >= 128 * K) return;
    int n = idx / K;
    int k = idx % K;
    int h = k & 7, t = (k >> 3) & 1, i = k >> 4;
    float w = W[(((size_t)t * 128 + n) * in_dim + i) * 8 + h];
    __half hi = __float2half_rn(w);
    __half lo = __float2half_rn(w - __half2float(hi));
    bhi[idx] = hi;
    blo[idx] = lo;
}
__global__ void transpose_wr(const float* __restrict__ W, float* __restrict__ Wt) {
    int idx = blockIdx.x * blockDim.x + threadIdx.x;
    if (idx >= 2048 * 32) return;
    int o = idx % 32;
    int k = idx / 32;
    int h = k & 7, t = (k >> 3) & 1, i = k >> 4;
    Wt[idx] = W[(((size_t)t * 32 + o) * 128 + i) * 8 + h];
}

// ---------------- fp16 hi/lo packing ----------------
__device__ __forceinline__ void cvt8h(const float* f, uint4& hi, uint4& lo) {
    uint32_t h[4], l[4];
#pragma unroll
    for (int j = 0; j < 4; ++j) {
        float a = f[2 * j], b = f[2 * j + 1];
        __half ah = __float2half_rn(a), bh = __float2half_rn(b);
        float ar = a - __half2float(ah);
        float br = b - __half2float(bh);
        __half2 hp; hp.x = ah; hp.y = bh;
        __half2 lp = __floats2half2_rn(ar, br);
        h[j] = *reinterpret_cast<uint32_t*>(&hp);
        l[j] = *reinterpret_cast<uint32_t*>(&lp);
    }
    hi = make_uint4(h[0], h[1], h[2], h[3]);
    lo = make_uint4(l[0], l[1], l[2], l[3]);
}

// ---------------- phi expansion (Chebyshev) ----------------
__device__ __forceinline__ void phi_expand(float x, float* cv, float* sv) {
    float s1, c1;
    sincosf(x, &s1, &c1);
    cv[0] = c1; sv[0] = s1;
    const float t2 = 2.0f * c1;
    float cp = 1.0f, sp = 0.0f;
#pragma unroll
    for (int h = 1; h < 8; ++h) {
        float cn = t2 * cv[h - 1] - cp;
        float sn = t2 * sv[h - 1] - sp;
        cp = cv[h - 1]; sp = sv[h - 1];
        cv[h] = cn; sv[h] = sn;
    }
}

// ---------------- HMMA KAN GEMM: fp16 3-term, mixed accumulators ----------------
// A = Ah+Al fp16 (~22 bit), B = Bh+Bl fp16 (~22 bit).
// AhBh -> fp32 acc; AlBh, AhBl -> fp16 acc (flushed to fp32 every chunk).
// Block 128x128, 4 warps, warp tile 64x64; cp.async B double-buffer.
__global__ __launch_bounds__(128, 2)
void kan_hmma(const float* __restrict__ in, int in_dim,
              const __half* __restrict__ bhi, const __half* __restrict__ blo,
              const float* __restrict__ in_scale, const float* __restrict__ out_scale,
              float* __restrict__ out) {
    extern __shared__ char smem[];
    const uint32_t smem_base = smem_to_u32(smem);
    const int A_HI = 0, A_LO = 16384;
    const int B_HI0 = 32768, B_LO0 = 49152;   // + stage*32768

    const int tid  = threadIdx.x;
    const int wid  = tid >> 5, lane = tid & 31;
    const int row0 = blockIdx.x * 128;

    const int m0 = (wid >> 1) * 64;
    const int n0 = (wid & 1) * 64;

    float acc[4][8][4];
    uint32_t lacc[4][8][2];
#pragma unroll
    for (int a = 0; a < 4; a++)
#pragma unroll
        for (int b = 0; b < 8; b++) {
#pragma unroll
            for (int c2 = 0; c2 < 4; c2++) acc[a][b][c2] = 0.0f;
            lacc[a][b][0] = 0u; lacc[a][b][1] = 0u;
        }

    const int arow = tid;
    const int grow = row0 + arow;
    const bool rv  = grow < NN;
    const float isc = (rv && in_scale) ? in_scale[grow] : 1.0f;
    const int Kb = in_dim * 32;
    const int nchunks = in_dim / 4;

    {
        const char* ph = (const char*)bhi;
        const char* pl = (const char*)blo;
#pragma unroll
        for (int r = 0; r < 8; ++r) {
            int idx = tid + 128 * r;
            int n = idx >> 3, seg = idx & 7;
            uint32_t so = SWZ((uint32_t)(n * 128 + seg * 16));
            CP_ASYNC16(smem_base + B_HI0 + so, ph + (size_t)n * Kb + seg * 16);
            CP_ASYNC16(smem_base + B_LO0 + so, pl + (size_t)n * Kb + seg * 16);
        }
        CP_COMMIT();
    }

    for (int c = 0; c < nchunks; ++c) {
        __syncthreads();
        if (c + 1 < nchunks) {
            const int st = ((c + 1) & 1) * 32768;
            const char* ph = (const char*)bhi + (c + 1) * 128;
            const char* pl = (const char*)blo + (c + 1) * 128;
#pragma unroll
            for (int r = 0; r < 8; ++r) {
                int idx = tid + 128 * r;
                int n = idx >> 3, seg = idx & 7;
                uint32_t so = SWZ((uint32_t)(n * 128 + seg * 16));
                CP_ASYNC16(smem_base + B_HI0 + st + so, ph + (size_t)n * Kb + seg * 16);
                CP_ASYNC16(smem_base + B_LO0 + st + so, pl + (size_t)n * Kb + seg * 16);
            }
        }
        CP_COMMIT();
        // --- A tile: phi expansion, fp16 hi/lo, SW128 swizzled ---
#pragma unroll
        for (int il = 0; il < 4; ++il) {
            float x = rv ? in[(size_t)grow * in_dim + c * 4 + il] * isc : 0.0f;
            float cv[8], sv[8];
            phi_expand(x, cv, sv);
            uint4 chi, clo, shi, slo;
            cvt8h(cv, chi, clo);
            cvt8h(sv, shi, slo);
            const uint32_t bo = (uint32_t)(arow * 128 + il * 32);
            *reinterpret_cast<uint4*>(smem + A_HI + SWZ(bo))      = chi;
            *reinterpret_cast<uint4*>(smem + A_LO + SWZ(bo))      = clo;
            *reinterpret_cast<uint4*>(smem + A_HI + SWZ(bo + 16)) = shi;
            *reinterpret_cast<uint4*>(smem + A_LO + SWZ(bo + 16)) = slo;
        }
        CP_WAIT1();
        __syncthreads();
        const int BH = B_HI0 + (c & 1) * 32768;
        const int BL = B_LO0 + (c & 1) * 32768;
#pragma unroll
        for (int kk = 0; kk < 4; ++kk) {
            const uint32_t kb = kk * 32;
            uint32_t bb[8][2];
            // ---- phase 1: Bh; AhBh->f32, AlBh->f16 ----
#pragma unroll
            for (int nt = 0; nt < 8; ++nt) {
                uint32_t addr = smem_base + SWZ((uint32_t)((n0 + nt * 8 + (lane & 7)) * 128 + kb + (((lane & 15) >> 3) & 1) * 16));
                LDSM2(bb[nt], addr + BH);
            }
#pragma unroll
            for (int mt = 0; mt < 4; ++mt) {
                uint32_t addr = smem_base + SWZ((uint32_t)((m0 + mt * 16 + (lane & 15)) * 128 + kb + (lane >> 4) * 16));
                uint32_t ah[4], al[4];
                LDSM4(ah, addr + A_HI);
                LDSM4(al, addr + A_LO);
#pragma unroll
                for (int nt = 0; nt < 8; ++nt) MMA_F32(acc[mt][nt], ah, bb[nt]);
#pragma unroll
                for (int nt = 0; nt < 8; ++nt) MMA_F16(lacc[mt][nt], al, bb[nt]);
            }
            // ---- phase 2: Bl; AhBl->f16 (reuse bb regs) ----
#pragma unroll
            for (int nt = 0; nt < 8; ++nt) {
                uint32_t addr = smem_base + SWZ((uint32_t)((n0 + nt * 8 + (lane & 7)) * 128 + kb + (((lane & 15) >> 3) & 1) * 16));
                LDSM2(bb[nt], addr + BL);
            }
#pragma unroll
            for (int mt = 0; mt < 4; ++mt) {
                uint32_t addr = smem_base + SWZ((uint32_t)((m0 + mt * 16 + (lane & 15)) * 128 + kb + (lane >> 4) * 16));
                uint32_t ah[4];
                LDSM4(ah, addr + A_HI);
#pragma unroll
                for (int nt = 0; nt < 8; ++nt) MMA_F16(lacc[mt][nt], ah, bb[nt]);
            }
        }
        // ---- flush fp16 correction accumulators into fp32 ----
#pragma unroll
        for (int mt = 0; mt < 4; ++mt)
#pragma unroll
            for (int nt = 0; nt < 8; ++nt) {
                __half2 p0 = *reinterpret_cast<__half2*>(&lacc[mt][nt][0]);
                __half2 p1 = *reinterpret_cast<__half2*>(&lacc[mt][nt][1]);
                float2 f0 = __half22float2(p0);
                float2 f1 = __half22float2(p1);
                acc[mt][nt][0] += f0.x;
                acc[mt][nt][1] += f0.y;
                acc[mt][nt][2] += f1.x;
                acc[mt][nt][3] += f1.y;
                lacc[mt][nt][0] = 0u;
                lacc[mt][nt][1] = 0u;
            }
    }

    // --- epilogue ---
    const int g4 = lane >> 2, t4 = lane & 3;
#pragma unroll
    for (int mt = 0; mt < 4; ++mt) {
        int r0 = row0 + m0 + mt * 16 + g4;
        int r1 = r0 + 8;
        float sc0 = 1.0f, sc1 = 1.0f;
        bool v0 = r0 < NN, v1 = r1 < NN;
        if (out_scale) {
            if (v0) sc0 = out_scale[r0];
            if (v1) sc1 = out_scale[r1];
        }
#pragma unroll
        for (int nt = 0; nt < 8; ++nt) {
            int col = n0 + nt * 8 + t4 * 2;
            if (v0) {
                float2* p = reinterpret_cast<float2*>(out + (size_t)r0 * 128 + col);
                *p = make_float2(acc[mt][nt][0] * sc0, acc[mt][nt][1] * sc0);
            }
            if (v1) {
                float2* p = reinterpret_cast<float2*>(out + (size_t)r1 * 128 + col);
                *p = make_float2(acc[mt][nt][2] * sc1, acc[mt][nt][3] * sc1);
            }
        }
    }
}

// ---------------- CSR aggregation ----------------
__global__ void aggregate(const float* __restrict__ hf,
                          const int* __restrict__ off, const int* __restrict__ srcv,
                          float* __restrict__ out) {
    int warp = (blockIdx.x * blockDim.x + threadIdx.x) >> 5;
    int lane = threadIdx.x & 31;
    if (warp >= NN) return;
    int e  = off[warp];
    int e1 = off[warp + 1];
    float4 a0 = make_float4(0.f, 0.f, 0.f, 0.f);
    float4 a1 = make_float4(0.f, 0.f, 0.f, 0.f);
    for (; e + 1 < e1; e += 2) {
        int r0 = __ldg(&srcv[e]);
        int r1 = __ldg(&srcv[e + 1]);
        float4 v0 = *reinterpret_cast<const float4*>(hf + (size_t)r0 * 128 + lane * 4);
        float4 v1 = *reinterpret_cast<const float4*>(hf + (size_t)r1 * 128 + lane * 4);
        a0.x += v0.x; a0.y += v0.y; a0.z += v0.z; a0.w += v0.w;
        a1.x += v1.x; a1.y += v1.y; a1.z += v1.z; a1.w += v1.w;
    }
    if (e < e1) {
        int r0 = __ldg(&srcv[e]);
        float4 v0 = *reinterpret_cast<const float4*>(hf + (size_t)r0 * 128 + lane * 4);
        a0.x += v0.x; a0.y += v0.y; a0.z += v0.z; a0.w += v0.w;
    }
    a0.x += a1.x; a0.y += a1.y; a0.z += a1.z; a0.w += a1.w;
    *reinterpret_cast<float4*>(out + (size_t)warp * 128 + lane * 4) = a0;
}

// ---------------- pooling ----------------
__global__ void pool_kernel(const float* __restrict__ h, const int* __restrict__ batch,
                            const float* __restrict__ dinv,
                            float* __restrict__ sums, float* __restrict__ cnts) {
    const int PER = 25;
    int warp = (blockIdx.x * blockDim.x + threadIdx.x) >> 5;
    int lane = threadIdx.x & 31;
    int n0 = warp * PER;
    if (n0 >= NN) return;
    int n1 = n0 + PER;
    if (n1 > NN) n1 = NN;
    float4 acc = make_float4(0.f, 0.f, 0.f, 0.f);
    float cnt = 0.f;
    int cg = batch[n0];
    for (int n = n0; n < n1; n++) {
        int g = batch[n];
        if (g != cg) {
            float* p = sums + (size_t)cg * 128 + lane * 4;
            atomicAdd(p + 0, acc.x); atomicAdd(p + 1, acc.y);
            atomicAdd(p + 2, acc.z); atomicAdd(p + 3, acc.w);
            if (lane == 0) atomicAdd(&cnts[cg], cnt);
            acc = make_float4(0.f, 0.f, 0.f, 0.f);
            cnt = 0.f; cg = g;
        }
        float w = dinv[n];
        float4 v = *reinterpret_cast<const float4*>(h + (size_t)n * 128 + lane * 4);
        acc.x += w * v.x; acc.y += w * v.y; acc.z += w * v.z; acc.w += w * v.w;
        cnt += 1.f;
    }
    float* p = sums + (size_t)cg * 128 + lane * 4;
    atomicAdd(p + 0, acc.x); atomicAdd(p + 1, acc.y);
    atomicAdd(p + 2, acc.z); atomicAdd(p + 3, acc.w);
    if (lane == 0) atomicAdd(&cnts[cg], cnt);
}

// ---------------- readout ----------------
__global__ void readout_kernel(const float* __restrict__ sums, const float* __restrict__ cnts,
                               const float* __restrict__ Wt,
                               float* __restrict__ out) {
    __shared__ float phi[2048];
    __shared__ float red[4][32];
    const int g = blockIdx.x;
    const int tid = threadIdx.x;     // 128 threads
    float cnt = fmaxf(cnts[g], 1.0f);
    float x = sums[(size_t)g * 128 + tid] / cnt;
    float cv[8], sv[8];
    phi_expand(x, cv, sv);
#pragma unroll
    for (int h = 0; h < 8; h++) {
        phi[tid * 16 + h]     = cv[h];
        phi[tid * 16 + 8 + h] = sv[h];
    }
    __syncthreads();
    const int o = tid & 31;
    const int part = tid >> 5;
    float acc = 0.f;
    int k0 = part * 512;
#pragma unroll 8
    for (int k = k0; k < k0 + 512; k++) acc += phi[k] * Wt[k * 32 + o];
    red[part][o] = acc;
    __syncthreads();
    if (tid < 32)
        out[(size_t)g * 32 + tid] = red[0][tid] + red[1][tid] + red[2][tid] + red[3][tid];
}

// ---------------- launch ----------------
extern "C" void kernel_launch(void* const* d_in, const int* in_sizes, int n_in,
                              void* d_out, int out_size) {
    const float* features = (const float*)d_in[0];   // [N,64]
    const int*   edges    = (const int*)d_in[1];     // [2,E]
    const int*   batch    = (const int*)d_in[2];     // [N]
    const float* W_embed  = (const float*)d_in[3];   // [2,128,64,8]
    const float* W_mp     = (const float*)d_in[4];   // [3,2,128,128,8]
    const float* W_read   = (const float*)d_in[5];   // [2,32,128,8]
    float* out = (float*)d_out;                      // [64,32]

    float *h0, *h1, *hf, *dinv, *wtr, *sums, *cnts;
    int *deg, *off, *cur, *srcv, *bsum, *boff;
    __half *bhe, *ble, *bhm, *blm;
    cudaGetSymbolAddress((void**)&h0,   g_h0);
    cudaGetSymbolAddress((void**)&h1,   g_h1);
    cudaGetSymbolAddress((void**)&hf,   g_hf);
    cudaGetSymbolAddress((void**)&dinv, g_dinv);
    cudaGetSymbolAddress((void**)&deg,  g_deg);
    cudaGetSymbolAddress((void**)&off,  g_off);
    cudaGetSymbolAddress((void**)&cur,  g_cur);
    cudaGetSymbolAddress((void**)&srcv, g_srcv);
    cudaGetSymbolAddress((void**)&bsum, g_bsum);
    cudaGetSymbolAddress((void**)&boff, g_boff);
    cudaGetSymbolAddress((void**)&bhe,  g_bhe);
    cudaGetSymbolAddress((void**)&ble,  g_ble);
    cudaGetSymbolAddress((void**)&bhm,  g_bhm);
    cudaGetSymbolAddress((void**)&blm,  g_blm);
    cudaGetSymbolAddress((void**)&wtr,  g_wtr);
    cudaGetSymbolAddress((void**)&sums, g_sums);
    cudaGetSymbolAddress((void**)&cnts, g_cnts);

    const int* erow = edges;
    const int* ecol = edges + EE;

    cudaFuncSetAttribute(kan_hmma, cudaFuncAttributeMaxDynamicSharedMemorySize, 98304);

    const int gblocks = (NN + 127) / 128;   // 391
    const int agg_blocks = (NN * 32 + 255) / 256;

    // Launch order: embed GEMM is MY 4th launch (harness prepends 2; ncu -s 5 hits it)
    make_b_embed<<<(128 * 1024 + 255) / 256, 256>>>(W_embed, bhe, ble, deg, sums, cnts);
    make_b<<<(128 * 2048 + 255) / 256, 256>>>(W_mp, bhm, blm, 128);
    transpose_wr<<<(2048 * 32 + 255) / 256, 256>>>(W_read, wtr);

    // embed: h0 = kan(features)   [ncu target]
    kan_hmma<<<gblocks, 128, 98304>>>(features, 64, bhe, ble, nullptr, nullptr, h0);

    // remaining weight prep
    for (int l = 1; l < 3; l++)
        make_b<<<(128 * 2048 + 255) / 256, 256>>>(
            W_mp + (size_t)l * 2 * 128 * 128 * 8,
            bhm + (size_t)l * 128 * 2048, blm + (size_t)l * 128 * 2048, 128);

    // ---- CSR build ----
    count_deg<<<(EE + 255) / 256, 256>>>(ecol, deg);
    const int nb = (NN + 255) / 256;  // 196
    deg_bsum<<<nb, 256>>>(deg, bsum, dinv);
    scan_bsum<<<1, 256>>>(bsum, boff, nb, off);
    scan_write<<<nb, 256>>>(deg, boff, off, cur);
    fill_csr<<<(EE + NN + 255) / 256, 256>>>(erow, ecol, cur, srcv);

    // mp 0
    kan_hmma<<<gblocks, 128, 98304>>>(h0, 128, bhm, blm, nullptr, dinv, hf);
    aggregate<<<agg_blocks, 256>>>(hf, off, srcv, h1);
    // mp 1
    kan_hmma<<<gblocks, 128, 98304>>>(h1, 128, bhm + 128 * 2048, blm + 128 * 2048, dinv, dinv, hf);
    aggregate<<<agg_blocks, 256>>>(hf, off, srcv, h0);
    // mp 2
    kan_hmma<<<gblocks, 128, 98304>>>(h0, 128, bhm + 2 * 128 * 2048, blm + 2 * 128 * 2048, dinv, dinv, hf);
    aggregate<<<agg_blocks, 256>>>(hf, off, srcv, h1);

    // pool + readout
    pool_kernel<<<250, 256>>>(h1, batch, dinv, sums, cnts);
    readout_kernel<<<GG, 128>>>(sums, cnts, wtr, out);
}

// round 14
// speedup vs baseline: 1.1671x; 1.1671x over previous
#include <cuda_runtime.h>
#include <cuda_fp16.h>
#include <math.h>
#include <stdint.h>

// ---------------- problem constants ----------------
#define NN   50000
#define EE   1600000
#define GG   64

// ---------------- device scratch (no allocation allowed) ----------------
__device__ float g_h0[(size_t)NN * 128];
__device__ float g_h1[(size_t)NN * 128];
__device__ float g_hf[(size_t)NN * 128];
__device__ float g_dinv[NN];
__device__ int   g_deg[NN];
__device__ int   g_off[NN + 1];
__device__ int   g_cur[NN];
__device__ int   g_srcv[EE + NN];
__device__ int   g_bsum[256];
__device__ int   g_boff[256];
__device__ __half g_bhe[128 * 1024];          // embed B hi fp16 [n][k]
__device__ __half g_ble[128 * 1024];          // embed B lo fp16
__device__ __half g_bhm[3 * 128 * 2048];      // mp B hi fp16 x3 (mp2 uses hi only)
__device__ __half g_blm[3 * 128 * 2048];      // mp B lo fp16 x3
__device__ float g_wtr[2048 * 32];            // readout [k][o] fp32
__device__ float g_sums[GG * 128];
__device__ float g_cnts[GG];

// ---------------- helpers ----------------
__device__ __forceinline__ uint32_t smem_to_u32(const void* p) {
    uint32_t a;
    asm("{ .reg .u64 t; cvta.to.shared.u64 t, %1; cvt.u32.u64 %0, t; }" : "=r"(a) : "l"(p));
    return a;
}
#define SWZ(x) ((x) ^ (((x) >> 3) & 0x70))

#define LDSM4(R, addr)                                                           \
    asm volatile("ldmatrix.sync.aligned.m8n8.x4.shared.b16 {%0,%1,%2,%3}, [%4];" \
                 : "=r"((R)[0]), "=r"((R)[1]), "=r"((R)[2]), "=r"((R)[3])        \
                 : "r"(addr))
#define LDSM2(R, addr)                                                           \
    asm volatile("ldmatrix.sync.aligned.m8n8.x2.shared.b16 {%0,%1}, [%2];"       \
                 : "=r"((R)[0]), "=r"((R)[1]) : "r"(addr))
#define MMA_F32(D, A, B)                                                         \
    asm volatile("mma.sync.aligned.m16n8k16.row.col.f32.f16.f16.f32 "            \
                 "{%0,%1,%2,%3}, {%4,%5,%6,%7}, {%8,%9}, {%0,%1,%2,%3};"         \
                 : "+f"((D)[0]), "+f"((D)[1]), "+f"((D)[2]), "+f"((D)[3])        \
                 : "r"((A)[0]), "r"((A)[1]), "r"((A)[2]), "r"((A)[3]),           \
                   "r"((B)[0]), "r"((B)[1]))
#define CP_ASYNC16(sa, gp)                                                       \
    asm volatile("cp.async.ca.shared.global [%0], [%1], 16;" :: "r"(sa), "l"(gp))
#define CP_COMMIT() asm volatile("cp.async.commit_group;" ::: "memory")
#define CP_WAIT1()  asm volatile("cp.async.wait_group 1;" ::: "memory")

// ---------------- prep kernels ----------------
__global__ void count_deg(const int* __restrict__ ecol, int* __restrict__ deg) {
    int e = blockIdx.x * blockDim.x + threadIdx.x;
    if (e < EE) atomicAdd(&deg[ecol[e]], 1);
}

__global__ void deg_bsum(const int* __restrict__ deg, int* __restrict__ bsum,
                         float* __restrict__ dinv) {
    __shared__ int sh[256];
    int t = threadIdx.x;
    int i = blockIdx.x * 256 + t;
    int d = (i < NN) ? deg[i] + 1 : 0;
    if (i < NN) dinv[i] = rsqrtf((float)d);
    sh[t] = d;
    __syncthreads();
    for (int s = 128; s > 0; s >>= 1) {
        if (t < s) sh[t] += sh[t + s];
        __syncthreads();
    }
    if (t == 0) bsum[blockIdx.x] = sh[0];
}
__global__ void scan_bsum(const int* __restrict__ bsum, int* __restrict__ boff,
                          int nb, int* __restrict__ off) {
    __shared__ int sh[256];
    int t = threadIdx.x;
    int v = (t < nb) ? bsum[t] : 0;
    sh[t] = v;
    __syncthreads();
    for (int d = 1; d < 256; d <<= 1) {
        int u = (t >= d) ? sh[t - d] : 0;
        __syncthreads();
        sh[t] += u;
        __syncthreads();
    }
    if (t < nb) boff[t] = sh[t] - v;
    if (t == 0) off[NN] = EE + NN;
}
__global__ void scan_write(const int* __restrict__ deg, const int* __restrict__ boff,
                           int* __restrict__ off, int* __restrict__ cur) {
    __shared__ int sh[256];
    int t = threadIdx.x;
    int i = blockIdx.x * 256 + t;
    int v = (i < NN) ? deg[i] + 1 : 0;
    sh[t] = v;
    __syncthreads();
    for (int d = 1; d < 256; d <<= 1) {
        int u = (t >= d) ? sh[t - d] : 0;
        __syncthreads();
        sh[t] += u;
        __syncthreads();
    }
    if (i < NN) {
        int o = boff[blockIdx.x] + sh[t] - v;
        off[i] = o;
        cur[i] = o;
    }
}
__global__ void fill_csr(const int* __restrict__ erow, const int* __restrict__ ecol,
                         int* __restrict__ cur, int* __restrict__ srcv) {
    int e = blockIdx.x * blockDim.x + threadIdx.x;
    if (e >= EE + NN) return;
    int r, c;
    if (e < EE) { r = erow[e]; c = ecol[e]; }
    else        { r = c = e - EE; }
    int p = atomicAdd(&cur[c], 1);
    srcv[p] = r;
}

// W[2][out=128][in=64][8] -> fp16 hi/lo; fuses deg/sums/cnts zeroing.
__global__ void make_b_embed(const float* __restrict__ W, __half* __restrict__ bhi,
                             __half* __restrict__ blo,
                             int* __restrict__ deg, float* __restrict__ sums,
                             float* __restrict__ cnts) {
    const int in_dim = 64;
    int idx = blockIdx.x * blockDim.x + threadIdx.x;
    if (idx < NN) deg[idx] = 0;
    if (idx < GG * 128) sums[idx] = 0.0f;
    if (idx < GG) cnts[idx] = 0.0f;
    int K = in_dim * 16;
    if (idx >= 128 * K) return;
    int n = idx / K;
    int k = idx % K;
    int h = k & 7, t = (k >> 3) & 1, i = k >> 4;
    float w = W[(((size_t)t * 128 + n) * in_dim + i) * 8 + h];
    __half hi = __float2half_rn(w);
    __half lo = __float2half_rn(w - __half2float(hi));
    bhi[idx] = hi;
    blo[idx] = lo;
}
// All 3 mp layers in one launch: W_mp[3][2][128][128][8] -> hi/lo [3][128][2048]
__global__ void make_b_mp(const float* __restrict__ W, __half* __restrict__ bhi,
                          __half* __restrict__ blo) {
    const int in_dim = 128;
    const int per = 128 * 2048;
    int idx = blockIdx.x * blockDim.x + threadIdx.x;
    if (idx >= 3 * per) return;
    int layer = idx / per;
    int li = idx % per;
    int K = in_dim * 16;
    int n = li / K;
    int k = li % K;
    int h = k & 7, t = (k >> 3) & 1, i = k >> 4;
    float w = W[(size_t)layer * 2 * 128 * 128 * 8 +
                (((size_t)t * 128 + n) * in_dim + i) * 8 + h];
    __half hi = __float2half_rn(w);
    __half lo = __float2half_rn(w - __half2float(hi));
    bhi[idx] = hi;
    blo[idx] = lo;
}
__global__ void transpose_wr(const float* __restrict__ W, float* __restrict__ Wt) {
    int idx = blockIdx.x * blockDim.x + threadIdx.x;
    if (idx >= 2048 * 32) return;
    int o = idx % 32;
    int k = idx / 32;
    int h = k & 7, t = (k >> 3) & 1, i = k >> 4;
    Wt[idx] = W[(((size_t)t * 32 + o) * 128 + i) * 8 + h];
}

// ---------------- fp16 hi/lo packing ----------------
__device__ __forceinline__ void cvt8h(const float* f, uint4& hi, uint4& lo) {
    uint32_t h[4], l[4];
#pragma unroll
    for (int j = 0; j < 4; ++j) {
        float a = f[2 * j], b = f[2 * j + 1];
        __half ah = __float2half_rn(a), bh = __float2half_rn(b);
        float ar = a - __half2float(ah);
        float br = b - __half2float(bh);
        __half2 hp; hp.x = ah; hp.y = bh;
        __half2 lp = __floats2half2_rn(ar, br);
        h[j] = *reinterpret_cast<uint32_t*>(&hp);
        l[j] = *reinterpret_cast<uint32_t*>(&lp);
    }
    hi = make_uint4(h[0], h[1], h[2], h[3]);
    lo = make_uint4(l[0], l[1], l[2], l[3]);
}

// ---------------- phi expansion (Chebyshev) ----------------
__device__ __forceinline__ void phi_expand(float x, float* cv, float* sv) {
    float s1, c1;
    sincosf(x, &s1, &c1);
    cv[0] = c1; sv[0] = s1;
    const float t2 = 2.0f * c1;
    float cp = 1.0f, sp = 0.0f;
#pragma unroll
    for (int h = 1; h < 8; ++h) {
        float cn = t2 * cv[h - 1] - cp;
        float sn = t2 * sv[h - 1] - sp;
        cp = cv[h - 1]; sp = sv[h - 1];
        cv[h] = cn; sv[h] = sn;
    }
}

// ---------------- HMMA KAN GEMM: fp16 3-term, all f32 acc (embed, mp0, mp1) ----
// A = Ah+Al fp16 (~22-bit), B = Bh+Bl fp16 (~22-bit); AhBh + AlBh + AhBl.
// Block 128x128, 4 warps, warp tile 64x64; cp.async B double-buffer.
__global__ __launch_bounds__(128, 2)
void kan_hmma(const float* __restrict__ in, int in_dim,
              const __half* __restrict__ bhi, const __half* __restrict__ blo,
              const float* __restrict__ in_scale, const float* __restrict__ out_scale,
              float* __restrict__ out) {
    extern __shared__ char smem[];
    const uint32_t smem_base = smem_to_u32(smem);
    const int A_HI = 0, A_LO = 16384;
    const int B_HI0 = 32768, B_LO0 = 49152;

    const int tid  = threadIdx.x;
    const int wid  = tid >> 5, lane = tid & 31;
    const int row0 = blockIdx.x * 128;

    const int m0 = (wid >> 1) * 64;
    const int n0 = (wid & 1) * 64;

    float acc[4][8][4];
#pragma unroll
    for (int a = 0; a < 4; a++)
#pragma unroll
        for (int b = 0; b < 8; b++)
#pragma unroll
            for (int c2 = 0; c2 < 4; c2++) acc[a][b][c2] = 0.0f;

    const int arow = tid;
    const int grow = row0 + arow;
    const bool rv  = grow < NN;
    const float isc = (rv && in_scale) ? in_scale[grow] : 1.0f;
    const int Kb = in_dim * 32;
    const int nchunks = in_dim / 4;

    {
        const char* ph = (const char*)bhi;
        const char* pl = (const char*)blo;
#pragma unroll
        for (int r = 0; r < 8; ++r) {
            int idx = tid + 128 * r;
            int n = idx >> 3, seg = idx & 7;
            uint32_t so = SWZ((uint32_t)(n * 128 + seg * 16));
            CP_ASYNC16(smem_base + B_HI0 + so, ph + (size_t)n * Kb + seg * 16);
            CP_ASYNC16(smem_base + B_LO0 + so, pl + (size_t)n * Kb + seg * 16);
        }
        CP_COMMIT();
    }

    for (int c = 0; c < nchunks; ++c) {
        __syncthreads();
        if (c + 1 < nchunks) {
            const int st = ((c + 1) & 1) * 32768;
            const char* ph = (const char*)bhi + (c + 1) * 128;
            const char* pl = (const char*)blo + (c + 1) * 128;
#pragma unroll
            for (int r = 0; r < 8; ++r) {
                int idx = tid + 128 * r;
                int n = idx >> 3, seg = idx & 7;
                uint32_t so = SWZ((uint32_t)(n * 128 + seg * 16));
                CP_ASYNC16(smem_base + B_HI0 + st + so, ph + (size_t)n * Kb + seg * 16);
                CP_ASYNC16(smem_base + B_LO0 + st + so, pl + (size_t)n * Kb + seg * 16);
            }
        }
        CP_COMMIT();
#pragma unroll
        for (int il = 0; il < 4; ++il) {
            float x = rv ? in[(size_t)grow * in_dim + c * 4 + il] * isc : 0.0f;
            float cv[8], sv[8];
            phi_expand(x, cv, sv);
            uint4 chi, clo, shi, slo;
            cvt8h(cv, chi, clo);
            cvt8h(sv, shi, slo);
            const uint32_t bo = (uint32_t)(arow * 128 + il * 32);
            *reinterpret_cast<uint4*>(smem + A_HI + SWZ(bo))      = chi;
            *reinterpret_cast<uint4*>(smem + A_LO + SWZ(bo))      = clo;
            *reinterpret_cast<uint4*>(smem + A_HI + SWZ(bo + 16)) = shi;
            *reinterpret_cast<uint4*>(smem + A_LO + SWZ(bo + 16)) = slo;
        }
        CP_WAIT1();
        __syncthreads();
        const int BH = B_HI0 + (c & 1) * 32768;
        const int BL = B_LO0 + (c & 1) * 32768;
#pragma unroll
        for (int kk = 0; kk < 4; ++kk) {
            const uint32_t kb = kk * 32;
            uint32_t bh[8][2], bl[8][2];
#pragma unroll
            for (int nt = 0; nt < 8; ++nt) {
                uint32_t addr = smem_base + SWZ((uint32_t)((n0 + nt * 8 + (lane & 7)) * 128 + kb + (((lane & 15) >> 3) & 1) * 16));
                LDSM2(bh[nt], addr + BH);
                LDSM2(bl[nt], addr + BL);
            }
#pragma unroll
            for (int mt = 0; mt < 4; ++mt) {
                uint32_t addr = smem_base + SWZ((uint32_t)((m0 + mt * 16 + (lane & 15)) * 128 + kb + (lane >> 4) * 16));
                uint32_t ah[4], al[4];
                LDSM4(ah, addr + A_HI);
                LDSM4(al, addr + A_LO);
#pragma unroll
                for (int nt = 0; nt < 8; ++nt) MMA_F32(acc[mt][nt], ah, bh[nt]);
#pragma unroll
                for (int nt = 0; nt < 8; ++nt) MMA_F32(acc[mt][nt], al, bh[nt]);
#pragma unroll
                for (int nt = 0; nt < 8; ++nt) MMA_F32(acc[mt][nt], ah, bl[nt]);
            }
        }
    }

    const int g4 = lane >> 2, t4 = lane & 3;
#pragma unroll
    for (int mt = 0; mt < 4; ++mt) {
        int r0 = row0 + m0 + mt * 16 + g4;
        int r1 = r0 + 8;
        float sc0 = 1.0f, sc1 = 1.0f;
        bool v0 = r0 < NN, v1 = r1 < NN;
        if (out_scale) {
            if (v0) sc0 = out_scale[r0];
            if (v1) sc1 = out_scale[r1];
        }
#pragma unroll
        for (int nt = 0; nt < 8; ++nt) {
            int col = n0 + nt * 8 + t4 * 2;
            if (v0) {
                float2* p = reinterpret_cast<float2*>(out + (size_t)r0 * 128 + col);
                *p = make_float2(acc[mt][nt][0] * sc0, acc[mt][nt][1] * sc0);
            }
            if (v1) {
                float2* p = reinterpret_cast<float2*>(out + (size_t)r1 * 128 + col);
                *p = make_float2(acc[mt][nt][2] * sc1, acc[mt][nt][3] * sc1);
            }
        }
    }
}

// ---------------- HMMA KAN GEMM: fp16 2-term (mp layer 2) ----------------
// A = Ah+Al fp16 (~22-bit), B single fp16 (the hi plane). 2 MMAs per k-step.
__global__ __launch_bounds__(128, 2)
void kan_hmma16(const float* __restrict__ in,
                const __half* __restrict__ bmat,
                const float* __restrict__ in_scale, const float* __restrict__ out_scale,
                float* __restrict__ out) {
    const int in_dim = 128;
    extern __shared__ char smem[];
    const uint32_t smem_base = smem_to_u32(smem);
    const int A_HI = 0, A_LO = 16384;
    const int B_M0 = 32768;   // stages at 32768 / 49152

    const int tid  = threadIdx.x;
    const int wid  = tid >> 5, lane = tid & 31;
    const int row0 = blockIdx.x * 128;

    const int m0 = (wid >> 1) * 64;
    const int n0 = (wid & 1) * 64;

    float acc[4][8][4];
#pragma unroll
    for (int a = 0; a < 4; a++)
#pragma unroll
        for (int b = 0; b < 8; b++)
#pragma unroll
            for (int c2 = 0; c2 < 4; c2++) acc[a][b][c2] = 0.0f;

    const int arow = tid;
    const int grow = row0 + arow;
    const bool rv  = grow < NN;
    const float isc = (rv && in_scale) ? in_scale[grow] : 1.0f;
    const int Kb = in_dim * 32;
    const int nchunks = in_dim / 4;

    {
        const char* pb = (const char*)bmat;
#pragma unroll
        for (int r = 0; r < 8; ++r) {
            int idx = tid + 128 * r;
            int n = idx >> 3, seg = idx & 7;
            uint32_t so = SWZ((uint32_t)(n * 128 + seg * 16));
            CP_ASYNC16(smem_base + B_M0 + so, pb + (size_t)n * Kb + seg * 16);
        }
        CP_COMMIT();
    }

    for (int c = 0; c < nchunks; ++c) {
        __syncthreads();
        if (c + 1 < nchunks) {
            const int st = ((c + 1) & 1) * 16384;
            const char* pb = (const char*)bmat + (c + 1) * 128;
#pragma unroll
            for (int r = 0; r < 8; ++r) {
                int idx = tid + 128 * r;
                int n = idx >> 3, seg = idx & 7;
                uint32_t so = SWZ((uint32_t)(n * 128 + seg * 16));
                CP_ASYNC16(smem_base + B_M0 + st + so, pb + (size_t)n * Kb + seg * 16);
            }
        }
        CP_COMMIT();
#pragma unroll
        for (int il = 0; il < 4; ++il) {
            float x = rv ? in[(size_t)grow * in_dim + c * 4 + il] * isc : 0.0f;
            float cv[8], sv[8];
            phi_expand(x, cv, sv);
            uint4 chi, clo, shi, slo;
            cvt8h(cv, chi, clo);
            cvt8h(sv, shi, slo);
            const uint32_t bo = (uint32_t)(arow * 128 + il * 32);
            *reinterpret_cast<uint4*>(smem + A_HI + SWZ(bo))      = chi;
            *reinterpret_cast<uint4*>(smem + A_LO + SWZ(bo))      = clo;
            *reinterpret_cast<uint4*>(smem + A_HI + SWZ(bo + 16)) = shi;
            *reinterpret_cast<uint4*>(smem + A_LO + SWZ(bo + 16)) = slo;
        }
        CP_WAIT1();
        __syncthreads();
        const int BM = B_M0 + (c & 1) * 16384;
#pragma unroll
        for (int kk = 0; kk < 4; ++kk) {
            const uint32_t kb = kk * 32;
            uint32_t bm[8][2];
#pragma unroll
            for (int nt = 0; nt < 8; ++nt) {
                uint32_t addr = smem_base + SWZ((uint32_t)((n0 + nt * 8 + (lane & 7)) * 128 + kb + (((lane & 15) >> 3) & 1) * 16));
                LDSM2(bm[nt], addr + BM);
            }
#pragma unroll
            for (int mt = 0; mt < 4; ++mt) {
                uint32_t addr = smem_base + SWZ((uint32_t)((m0 + mt * 16 + (lane & 15)) * 128 + kb + (lane >> 4) * 16));
                uint32_t ah[4], al[4];
                LDSM4(ah, addr + A_HI);
                LDSM4(al, addr + A_LO);
#pragma unroll
                for (int nt = 0; nt < 8; ++nt) MMA_F32(acc[mt][nt], ah, bm[nt]);
#pragma unroll
                for (int nt = 0; nt < 8; ++nt) MMA_F32(acc[mt][nt], al, bm[nt]);
            }
        }
    }

    const int g4 = lane >> 2, t4 = lane & 3;
#pragma unroll
    for (int mt = 0; mt < 4; ++mt) {
        int r0 = row0 + m0 + mt * 16 + g4;
        int r1 = r0 + 8;
        float sc0 = 1.0f, sc1 = 1.0f;
        bool v0 = r0 < NN, v1 = r1 < NN;
        if (out_scale) {
            if (v0) sc0 = out_scale[r0];
            if (v1) sc1 = out_scale[r1];
        }
#pragma unroll
        for (int nt = 0; nt < 8; ++nt) {
            int col = n0 + nt * 8 + t4 * 2;
            if (v0) {
                float2* p = reinterpret_cast<float2*>(out + (size_t)r0 * 128 + col);
                *p = make_float2(acc[mt][nt][0] * sc0, acc[mt][nt][1] * sc0);
            }
            if (v1) {
                float2* p = reinterpret_cast<float2*>(out + (size_t)r1 * 128 + col);
                *p = make_float2(acc[mt][nt][2] * sc1, acc[mt][nt][3] * sc1);
            }
        }
    }
}

// ---------------- CSR aggregation ----------------
__global__ void aggregate(const float* __restrict__ hf,
                          const int* __restrict__ off, const int* __restrict__ srcv,
                          float* __restrict__ out) {
    int warp = (blockIdx.x * blockDim.x + threadIdx.x) >> 5;
    int lane = threadIdx.x & 31;
    if (warp >= NN) return;
    int e  = off[warp];
    int e1 = off[warp + 1];
    float4 a0 = make_float4(0.f, 0.f, 0.f, 0.f);
    float4 a1 = make_float4(0.f, 0.f, 0.f, 0.f);
    for (; e + 1 < e1; e += 2) {
        int r0 = __ldg(&srcv[e]);
        int r1 = __ldg(&srcv[e + 1]);
        float4 v0 = *reinterpret_cast<const float4*>(hf + (size_t)r0 * 128 + lane * 4);
        float4 v1 = *reinterpret_cast<const float4*>(hf + (size_t)r1 * 128 + lane * 4);
        a0.x += v0.x; a0.y += v0.y; a0.z += v0.z; a0.w += v0.w;
        a1.x += v1.x; a1.y += v1.y; a1.z += v1.z; a1.w += v1.w;
    }
    if (e < e1) {
        int r0 = __ldg(&srcv[e]);
        float4 v0 = *reinterpret_cast<const float4*>(hf + (size_t)r0 * 128 + lane * 4);
        a0.x += v0.x; a0.y += v0.y; a0.z += v0.z; a0.w += v0.w;
    }
    a0.x += a1.x; a0.y += a1.y; a0.z += a1.z; a0.w += a1.w;
    *reinterpret_cast<float4*>(out + (size_t)warp * 128 + lane * 4) = a0;
}

// ---------------- pooling ----------------
__global__ void pool_kernel(const float* __restrict__ h, const int* __restrict__ batch,
                            const float* __restrict__ dinv,
                            float* __restrict__ sums, float* __restrict__ cnts) {
    const int PER = 25;
    int warp = (blockIdx.x * blockDim.x + threadIdx.x) >> 5;
    int lane = threadIdx.x & 31;
    int n0 = warp * PER;
    if (n0 >= NN) return;
    int n1 = n0 + PER;
    if (n1 > NN) n1 = NN;
    float4 acc = make_float4(0.f, 0.f, 0.f, 0.f);
    float cnt = 0.f;
    int cg = batch[n0];
    for (int n = n0; n < n1; n++) {
        int g = batch[n];
        if (g != cg) {
            float* p = sums + (size_t)cg * 128 + lane * 4;
            atomicAdd(p + 0, acc.x); atomicAdd(p + 1, acc.y);
            atomicAdd(p + 2, acc.z); atomicAdd(p + 3, acc.w);
            if (lane == 0) atomicAdd(&cnts[cg], cnt);
            acc = make_float4(0.f, 0.f, 0.f, 0.f);
            cnt = 0.f; cg = g;
        }
        float w = dinv[n];
        float4 v = *reinterpret_cast<const float4*>(h + (size_t)n * 128 + lane * 4);
        acc.x += w * v.x; acc.y += w * v.y; acc.z += w * v.z; acc.w += w * v.w;
        cnt += 1.f;
    }
    float* p = sums + (size_t)cg * 128 + lane * 4;
    atomicAdd(p + 0, acc.x); atomicAdd(p + 1, acc.y);
    atomicAdd(p + 2, acc.z); atomicAdd(p + 3, acc.w);
    if (lane == 0) atomicAdd(&cnts[cg], cnt);
}

// ---------------- readout ----------------
__global__ void readout_kernel(const float* __restrict__ sums, const float* __restrict__ cnts,
                               const float* __restrict__ Wt,
                               float* __restrict__ out) {
    __shared__ float phi[2048];
    __shared__ float red[4][32];
    const int g = blockIdx.x;
    const int tid = threadIdx.x;     // 128 threads
    float cnt = fmaxf(cnts[g], 1.0f);
    float x = sums[(size_t)g * 128 + tid] / cnt;
    float cv[8], sv[8];
    phi_expand(x, cv, sv);
#pragma unroll
    for (int h = 0; h < 8; h++) {
        phi[tid * 16 + h]     = cv[h];
        phi[tid * 16 + 8 + h] = sv[h];
    }
    __syncthreads();
    const int o = tid & 31;
    const int part = tid >> 5;
    float acc = 0.f;
    int k0 = part * 512;
#pragma unroll 8
    for (int k = k0; k < k0 + 512; k++) acc += phi[k] * Wt[k * 32 + o];
    red[part][o] = acc;
    __syncthreads();
    if (tid < 32)
        out[(size_t)g * 32 + tid] = red[0][tid] + red[1][tid] + red[2][tid] + red[3][tid];
}

// ---------------- launch ----------------
extern "C" void kernel_launch(void* const* d_in, const int* in_sizes, int n_in,
                              void* d_out, int out_size) {
    const float* features = (const float*)d_in[0];   // [N,64]
    const int*   edges    = (const int*)d_in[1];     // [2,E]
    const int*   batch    = (const int*)d_in[2];     // [N]
    const float* W_embed  = (const float*)d_in[3];   // [2,128,64,8]
    const float* W_mp     = (const float*)d_in[4];   // [3,2,128,128,8]
    const float* W_read   = (const float*)d_in[5];   // [2,32,128,8]
    float* out = (float*)d_out;                      // [64,32]

    float *h0, *h1, *hf, *dinv, *wtr, *sums, *cnts;
    int *deg, *off, *cur, *srcv, *bsum, *boff;
    __half *bhe, *ble, *bhm, *blm;
    cudaGetSymbolAddress((void**)&h0,   g_h0);
    cudaGetSymbolAddress((void**)&h1,   g_h1);
    cudaGetSymbolAddress((void**)&hf,   g_hf);
    cudaGetSymbolAddress((void**)&dinv, g_dinv);
    cudaGetSymbolAddress((void**)&deg,  g_deg);
    cudaGetSymbolAddress((void**)&off,  g_off);
    cudaGetSymbolAddress((void**)&cur,  g_cur);
    cudaGetSymbolAddress((void**)&srcv, g_srcv);
    cudaGetSymbolAddress((void**)&bsum, g_bsum);
    cudaGetSymbolAddress((void**)&boff, g_boff);
    cudaGetSymbolAddress((void**)&bhe,  g_bhe);
    cudaGetSymbolAddress((void**)&ble,  g_ble);
    cudaGetSymbolAddress((void**)&bhm,  g_bhm);
    cudaGetSymbolAddress((void**)&blm,  g_blm);
    cudaGetSymbolAddress((void**)&wtr,  g_wtr);
    cudaGetSymbolAddress((void**)&sums, g_sums);
    cudaGetSymbolAddress((void**)&cnts, g_cnts);

    const int* erow = edges;
    const int* ecol = edges + EE;

    cudaFuncSetAttribute(kan_hmma, cudaFuncAttributeMaxDynamicSharedMemorySize, 98304);
    cudaFuncSetAttribute(kan_hmma16, cudaFuncAttributeMaxDynamicSharedMemorySize, 65536);

    const int gblocks = (NN + 127) / 128;   // 391
    const int agg_blocks = (NN * 32 + 255) / 256;

    // Launch order: embed GEMM is MY 4th launch (harness prepends 2; ncu -s 5 hits it)
    make_b_embed<<<(128 * 1024 + 255) / 256, 256>>>(W_embed, bhe, ble, deg, sums, cnts);
    make_b_mp<<<(3 * 128 * 2048 + 255) / 256, 256>>>(W_mp, bhm, blm);
    transpose_wr<<<(2048 * 32 + 255) / 256, 256>>>(W_read, wtr);

    // embed: h0 = kan(features)   [ncu target]
    kan_hmma<<<gblocks, 128, 98304>>>(features, 64, bhe, ble, nullptr, nullptr, h0);

    // ---- CSR build ----
    count_deg<<<(EE + 255) / 256, 256>>>(ecol, deg);
    const int nb = (NN + 255) / 256;  // 196
    deg_bsum<<<nb, 256>>>(deg, bsum, dinv);
    scan_bsum<<<1, 256>>>(bsum, boff, nb, off);
    scan_write<<<nb, 256>>>(deg, boff, off, cur);
    fill_csr<<<(EE + NN + 255) / 256, 256>>>(erow, ecol, cur, srcv);

    // mp 0 (fp16 3-term)
    kan_hmma<<<gblocks, 128, 98304>>>(h0, 128, bhm, blm, nullptr, dinv, hf);
    aggregate<<<agg_blocks, 256>>>(hf, off, srcv, h1);
    // mp 1 (fp16 3-term)
    kan_hmma<<<gblocks, 128, 98304>>>(h1, 128, bhm + 128 * 2048, blm + 128 * 2048, dinv, dinv, hf);
    aggregate<<<agg_blocks, 256>>>(hf, off, srcv, h0);
    // mp 2 (fp16 2-term; B = hi plane of layer 2)
    kan_hmma16<<<gblocks, 128, 65536>>>(h0, bhm + 2 * 128 * 2048, dinv, dinv, hf);
    aggregate<<<agg_blocks, 256>>>(hf, off, srcv, h1);

    // pool + readout
    pool_kernel<<<250, 256>>>(h1, batch, dinv, sums, cnts);
    readout_kernel<<<GG, 128>>>(sums, cnts, wtr, out);
}

// round 15
// speedup vs baseline: 1.1847x; 1.0151x over previous
#include <cuda_runtime.h>
#include <cuda_fp16.h>
#include <math.h>
#include <stdint.h>

// ---------------- problem constants ----------------
#define NN   50000
#define EE   1600000
#define GG   64

// ---------------- device scratch (no allocation allowed) ----------------
__device__ float g_h0[(size_t)NN * 128];
__device__ float g_h1[(size_t)NN * 128];
__device__ float g_hf[(size_t)NN * 128];
__device__ float g_dinv[NN];
__device__ int   g_deg[NN];
__device__ int   g_off[NN + 1];
__device__ int   g_cur[NN];
__device__ int   g_srcv[EE + NN];
__device__ int   g_bsum[256];
__device__ int   g_boff[256];
__device__ __half g_bhe[128 * 1024];          // embed B hi fp16 [n][k]
__device__ __half g_ble[128 * 1024];          // embed B lo fp16
__device__ __half g_bhm[3 * 128 * 2048];      // mp B hi fp16 x3 (mp2 uses hi only)
__device__ __half g_blm[3 * 128 * 2048];      // mp B lo fp16 x3
__device__ float g_wtr[2048 * 32];            // readout [k][o] fp32
__device__ float g_sums[GG * 128];
__device__ float g_cnts[GG];

// ---------------- helpers ----------------
__device__ __forceinline__ uint32_t smem_to_u32(const void* p) {
    uint32_t a;
    asm("{ .reg .u64 t; cvta.to.shared.u64 t, %1; cvt.u32.u64 %0, t; }" : "=r"(a) : "l"(p));
    return a;
}
#define SWZ(x) ((x) ^ (((x) >> 3) & 0x70))

#define LDSM4(R, addr)                                                           \
    asm volatile("ldmatrix.sync.aligned.m8n8.x4.shared.b16 {%0,%1,%2,%3}, [%4];" \
                 : "=r"((R)[0]), "=r"((R)[1]), "=r"((R)[2]), "=r"((R)[3])        \
                 : "r"(addr))
#define LDSM2(R, addr)                                                           \
    asm volatile("ldmatrix.sync.aligned.m8n8.x2.shared.b16 {%0,%1}, [%2];"       \
                 : "=r"((R)[0]), "=r"((R)[1]) : "r"(addr))
#define MMA_F32(D, A, B)                                                         \
    asm volatile("mma.sync.aligned.m16n8k16.row.col.f32.f16.f16.f32 "            \
                 "{%0,%1,%2,%3}, {%4,%5,%6,%7}, {%8,%9}, {%0,%1,%2,%3};"         \
                 : "+f"((D)[0]), "+f"((D)[1]), "+f"((D)[2]), "+f"((D)[3])        \
                 : "r"((A)[0]), "r"((A)[1]), "r"((A)[2]), "r"((A)[3]),           \
                   "r"((B)[0]), "r"((B)[1]))
#define CP_ASYNC16(sa, gp)                                                       \
    asm volatile("cp.async.ca.shared.global [%0], [%1], 16;" :: "r"(sa), "l"(gp))
#define CP_COMMIT() asm volatile("cp.async.commit_group;" ::: "memory")
#define CP_WAIT1()  asm volatile("cp.async.wait_group 1;" ::: "memory")

// ---------------- prep kernels ----------------
__global__ void count_deg(const int* __restrict__ ecol, int* __restrict__ deg) {
    int e = blockIdx.x * blockDim.x + threadIdx.x;
    if (e < EE) atomicAdd(&deg[ecol[e]], 1);
}

__global__ void deg_bsum(const int* __restrict__ deg, int* __restrict__ bsum,
                         float* __restrict__ dinv) {
    __shared__ int sh[256];
    int t = threadIdx.x;
    int i = blockIdx.x * 256 + t;
    int d = (i < NN) ? deg[i] + 1 : 0;
    if (i < NN) dinv[i] = rsqrtf((float)d);
    sh[t] = d;
    __syncthreads();
    for (int s = 128; s > 0; s >>= 1) {
        if (t < s) sh[t] += sh[t + s];
        __syncthreads();
    }
    if (t == 0) bsum[blockIdx.x] = sh[0];
}
__global__ void scan_bsum(const int* __restrict__ bsum, int* __restrict__ boff,
                          int nb, int* __restrict__ off) {
    __shared__ int sh[256];
    int t = threadIdx.x;
    int v = (t < nb) ? bsum[t] : 0;
    sh[t] = v;
    __syncthreads();
    for (int d = 1; d < 256; d <<= 1) {
        int u = (t >= d) ? sh[t - d] : 0;
        __syncthreads();
        sh[t] += u;
        __syncthreads();
    }
    if (t < nb) boff[t] = sh[t] - v;
    if (t == 0) off[NN] = EE + NN;
}
__global__ void scan_write(const int* __restrict__ deg, const int* __restrict__ boff,
                           int* __restrict__ off, int* __restrict__ cur) {
    __shared__ int sh[256];
    int t = threadIdx.x;
    int i = blockIdx.x * 256 + t;
    int v = (i < NN) ? deg[i] + 1 : 0;
    sh[t] = v;
    __syncthreads();
    for (int d = 1; d < 256; d <<= 1) {
        int u = (t >= d) ? sh[t - d] : 0;
        __syncthreads();
        sh[t] += u;
        __syncthreads();
    }
    if (i < NN) {
        int o = boff[blockIdx.x] + sh[t] - v;
        off[i] = o;
        cur[i] = o;
    }
}
__global__ void fill_csr(const int* __restrict__ erow, const int* __restrict__ ecol,
                         int* __restrict__ cur, int* __restrict__ srcv) {
    int e = blockIdx.x * blockDim.x + threadIdx.x;
    if (e >= EE + NN) return;
    int r, c;
    if (e < EE) { r = erow[e]; c = ecol[e]; }
    else        { r = c = e - EE; }
    int p = atomicAdd(&cur[c], 1);
    srcv[p] = r;
}

// W[2][out=128][in=64][8] -> fp16 hi/lo; fuses deg/sums/cnts zeroing.
__global__ void make_b_embed(const float* __restrict__ W, __half* __restrict__ bhi,
                             __half* __restrict__ blo,
                             int* __restrict__ deg, float* __restrict__ sums,
                             float* __restrict__ cnts) {
    const int in_dim = 64;
    int idx = blockIdx.x * blockDim.x + threadIdx.x;
    if (idx < NN) deg[idx] = 0;
    if (idx < GG * 128) sums[idx] = 0.0f;
    if (idx < GG) cnts[idx] = 0.0f;
    int K = in_dim * 16;
    if (idx >= 128 * K) return;
    int n = idx / K;
    int k = idx % K;
    int h = k & 7, t = (k >> 3) & 1, i = k >> 4;
    float w = W[(((size_t)t * 128 + n) * in_dim + i) * 8 + h];
    __half hi = __float2half_rn(w);
    __half lo = __float2half_rn(w - __half2float(hi));
    bhi[idx] = hi;
    blo[idx] = lo;
}
// All 3 mp layers in one launch: W_mp[3][2][128][128][8] -> hi/lo [3][128][2048]
__global__ void make_b_mp(const float* __restrict__ W, __half* __restrict__ bhi,
                          __half* __restrict__ blo) {
    const int in_dim = 128;
    const int per = 128 * 2048;
    int idx = blockIdx.x * blockDim.x + threadIdx.x;
    if (idx >= 3 * per) return;
    int layer = idx / per;
    int li = idx % per;
    int K = in_dim * 16;
    int n = li / K;
    int k = li % K;
    int h = k & 7, t = (k >> 3) & 1, i = k >> 4;
    float w = W[(size_t)layer * 2 * 128 * 128 * 8 +
                (((size_t)t * 128 + n) * in_dim + i) * 8 + h];
    __half hi = __float2half_rn(w);
    __half lo = __float2half_rn(w - __half2float(hi));
    bhi[idx] = hi;
    blo[idx] = lo;
}
__global__ void transpose_wr(const float* __restrict__ W, float* __restrict__ Wt) {
    int idx = blockIdx.x * blockDim.x + threadIdx.x;
    if (idx >= 2048 * 32) return;
    int o = idx % 32;
    int k = idx / 32;
    int h = k & 7, t = (k >> 3) & 1, i = k >> 4;
    Wt[idx] = W[(((size_t)t * 32 + o) * 128 + i) * 8 + h];
}

// ---------------- fp16 hi/lo packing ----------------
__device__ __forceinline__ void cvt8h(const float* f, uint4& hi, uint4& lo) {
    uint32_t h[4], l[4];
#pragma unroll
    for (int j = 0; j < 4; ++j) {
        float a = f[2 * j], b = f[2 * j + 1];
        __half ah = __float2half_rn(a), bh = __float2half_rn(b);
        float ar = a - __half2float(ah);
        float br = b - __half2float(bh);
        __half2 hp; hp.x = ah; hp.y = bh;
        __half2 lp = __floats2half2_rn(ar, br);
        h[j] = *reinterpret_cast<uint32_t*>(&hp);
        l[j] = *reinterpret_cast<uint32_t*>(&lp);
    }
    hi = make_uint4(h[0], h[1], h[2], h[3]);
    lo = make_uint4(l[0], l[1], l[2], l[3]);
}

// ---------------- phi expansion (Chebyshev) ----------------
__device__ __forceinline__ void phi_expand(float x, float* cv, float* sv) {
    float s1, c1;
    sincosf(x, &s1, &c1);
    cv[0] = c1; sv[0] = s1;
    const float t2 = 2.0f * c1;
    float cp = 1.0f, sp = 0.0f;
#pragma unroll
    for (int h = 1; h < 8; ++h) {
        float cn = t2 * cv[h - 1] - cp;
        float sn = t2 * sv[h - 1] - sp;
        cp = cv[h - 1]; sp = sv[h - 1];
        cv[h] = cn; sv[h] = sn;
    }
}

// ---------------- HMMA KAN GEMM: fp16 3-term, all f32 acc (embed, mp0, mp1) ----
__global__ __launch_bounds__(128, 2)
void kan_hmma(const float* __restrict__ in, int in_dim,
              const __half* __restrict__ bhi, const __half* __restrict__ blo,
              const float* __restrict__ in_scale, const float* __restrict__ out_scale,
              float* __restrict__ out) {
    extern __shared__ char smem[];
    const uint32_t smem_base = smem_to_u32(smem);
    const int A_HI = 0, A_LO = 16384;
    const int B_HI0 = 32768, B_LO0 = 49152;

    const int tid  = threadIdx.x;
    const int wid  = tid >> 5, lane = tid & 31;
    const int row0 = blockIdx.x * 128;

    const int m0 = (wid >> 1) * 64;
    const int n0 = (wid & 1) * 64;

    float acc[4][8][4];
#pragma unroll
    for (int a = 0; a < 4; a++)
#pragma unroll
        for (int b = 0; b < 8; b++)
#pragma unroll
            for (int c2 = 0; c2 < 4; c2++) acc[a][b][c2] = 0.0f;

    const int arow = tid;
    const int grow = row0 + arow;
    const bool rv  = grow < NN;
    const float isc = (rv && in_scale) ? in_scale[grow] : 1.0f;
    const int Kb = in_dim * 32;
    const int nchunks = in_dim / 4;

    {
        const char* ph = (const char*)bhi;
        const char* pl = (const char*)blo;
#pragma unroll
        for (int r = 0; r < 8; ++r) {
            int idx = tid + 128 * r;
            int n = idx >> 3, seg = idx & 7;
            uint32_t so = SWZ((uint32_t)(n * 128 + seg * 16));
            CP_ASYNC16(smem_base + B_HI0 + so, ph + (size_t)n * Kb + seg * 16);
            CP_ASYNC16(smem_base + B_LO0 + so, pl + (size_t)n * Kb + seg * 16);
        }
        CP_COMMIT();
    }

    for (int c = 0; c < nchunks; ++c) {
        __syncthreads();
        if (c + 1 < nchunks) {
            const int st = ((c + 1) & 1) * 32768;
            const char* ph = (const char*)bhi + (c + 1) * 128;
            const char* pl = (const char*)blo + (c + 1) * 128;
#pragma unroll
            for (int r = 0; r < 8; ++r) {
                int idx = tid + 128 * r;
                int n = idx >> 3, seg = idx & 7;
                uint32_t so = SWZ((uint32_t)(n * 128 + seg * 16));
                CP_ASYNC16(smem_base + B_HI0 + st + so, ph + (size_t)n * Kb + seg * 16);
                CP_ASYNC16(smem_base + B_LO0 + st + so, pl + (size_t)n * Kb + seg * 16);
            }
        }
        CP_COMMIT();
#pragma unroll
        for (int il = 0; il < 4; ++il) {
            float x = rv ? in[(size_t)grow * in_dim + c * 4 + il] * isc : 0.0f;
            float cv[8], sv[8];
            phi_expand(x, cv, sv);
            uint4 chi, clo, shi, slo;
            cvt8h(cv, chi, clo);
            cvt8h(sv, shi, slo);
            const uint32_t bo = (uint32_t)(arow * 128 + il * 32);
            *reinterpret_cast<uint4*>(smem + A_HI + SWZ(bo))      = chi;
            *reinterpret_cast<uint4*>(smem + A_LO + SWZ(bo))      = clo;
            *reinterpret_cast<uint4*>(smem + A_HI + SWZ(bo + 16)) = shi;
            *reinterpret_cast<uint4*>(smem + A_LO + SWZ(bo + 16)) = slo;
        }
        CP_WAIT1();
        __syncthreads();
        const int BH = B_HI0 + (c & 1) * 32768;
        const int BL = B_LO0 + (c & 1) * 32768;
#pragma unroll
        for (int kk = 0; kk < 4; ++kk) {
            const uint32_t kb = kk * 32;
            uint32_t bh[8][2], bl[8][2];
#pragma unroll
            for (int nt = 0; nt < 8; ++nt) {
                uint32_t addr = smem_base + SWZ((uint32_t)((n0 + nt * 8 + (lane & 7)) * 128 + kb + (((lane & 15) >> 3) & 1) * 16));
                LDSM2(bh[nt], addr + BH);
                LDSM2(bl[nt], addr + BL);
            }
#pragma unroll
            for (int mt = 0; mt < 4; ++mt) {
                uint32_t addr = smem_base + SWZ((uint32_t)((m0 + mt * 16 + (lane & 15)) * 128 + kb + (lane >> 4) * 16));
                uint32_t ah[4], al[4];
                LDSM4(ah, addr + A_HI);
                LDSM4(al, addr + A_LO);
#pragma unroll
                for (int nt = 0; nt < 8; ++nt) MMA_F32(acc[mt][nt], ah, bh[nt]);
#pragma unroll
                for (int nt = 0; nt < 8; ++nt) MMA_F32(acc[mt][nt], al, bh[nt]);
#pragma unroll
                for (int nt = 0; nt < 8; ++nt) MMA_F32(acc[mt][nt], ah, bl[nt]);
            }
        }
    }

    const int g4 = lane >> 2, t4 = lane & 3;
#pragma unroll
    for (int mt = 0; mt < 4; ++mt) {
        int r0 = row0 + m0 + mt * 16 + g4;
        int r1 = r0 + 8;
        float sc0 = 1.0f, sc1 = 1.0f;
        bool v0 = r0 < NN, v1 = r1 < NN;
        if (out_scale) {
            if (v0) sc0 = out_scale[r0];
            if (v1) sc1 = out_scale[r1];
        }
#pragma unroll
        for (int nt = 0; nt < 8; ++nt) {
            int col = n0 + nt * 8 + t4 * 2;
            if (v0) {
                float2* p = reinterpret_cast<float2*>(out + (size_t)r0 * 128 + col);
                *p = make_float2(acc[mt][nt][0] * sc0, acc[mt][nt][1] * sc0);
            }
            if (v1) {
                float2* p = reinterpret_cast<float2*>(out + (size_t)r1 * 128 + col);
                *p = make_float2(acc[mt][nt][2] * sc1, acc[mt][nt][3] * sc1);
            }
        }
    }
}

// ---------------- HMMA KAN GEMM: fp16 2-term (mp layer 2) ----------------
__global__ __launch_bounds__(128, 2)
void kan_hmma16(const float* __restrict__ in,
                const __half* __restrict__ bmat,
                const float* __restrict__ in_scale, const float* __restrict__ out_scale,
                float* __restrict__ out) {
    const int in_dim = 128;
    extern __shared__ char smem[];
    const uint32_t smem_base = smem_to_u32(smem);
    const int A_HI = 0, A_LO = 16384;
    const int B_M0 = 32768;

    const int tid  = threadIdx.x;
    const int wid  = tid >> 5, lane = tid & 31;
    const int row0 = blockIdx.x * 128;

    const int m0 = (wid >> 1) * 64;
    const int n0 = (wid & 1) * 64;

    float acc[4][8][4];
#pragma unroll
    for (int a = 0; a < 4; a++)
#pragma unroll
        for (int b = 0; b < 8; b++)
#pragma unroll
            for (int c2 = 0; c2 < 4; c2++) acc[a][b][c2] = 0.0f;

    const int arow = tid;
    const int grow = row0 + arow;
    const bool rv  = grow < NN;
    const float isc = (rv && in_scale) ? in_scale[grow] : 1.0f;
    const int Kb = in_dim * 32;
    const int nchunks = in_dim / 4;

    {
        const char* pb = (const char*)bmat;
#pragma unroll
        for (int r = 0; r < 8; ++r) {
            int idx = tid + 128 * r;
            int n = idx >> 3, seg = idx & 7;
            uint32_t so = SWZ((uint32_t)(n * 128 + seg * 16));
            CP_ASYNC16(smem_base + B_M0 + so, pb + (size_t)n * Kb + seg * 16);
        }
        CP_COMMIT();
    }

    for (int c = 0; c < nchunks; ++c) {
        __syncthreads();
        if (c + 1 < nchunks) {
            const int st = ((c + 1) & 1) * 16384;
            const char* pb = (const char*)bmat + (c + 1) * 128;
#pragma unroll
            for (int r = 0; r < 8; ++r) {
                int idx = tid + 128 * r;
                int n = idx >> 3, seg = idx & 7;
                uint32_t so = SWZ((uint32_t)(n * 128 + seg * 16));
                CP_ASYNC16(smem_base + B_M0 + st + so, pb + (size_t)n * Kb + seg * 16);
            }
        }
        CP_COMMIT();
#pragma unroll
        for (int il = 0; il < 4; ++il) {
            float x = rv ? in[(size_t)grow * in_dim + c * 4 + il] * isc : 0.0f;
            float cv[8], sv[8];
            phi_expand(x, cv, sv);
            uint4 chi, clo, shi, slo;
            cvt8h(cv, chi, clo);
            cvt8h(sv, shi, slo);
            const uint32_t bo = (uint32_t)(arow * 128 + il * 32);
            *reinterpret_cast<uint4*>(smem + A_HI + SWZ(bo))      = chi;
            *reinterpret_cast<uint4*>(smem + A_LO + SWZ(bo))      = clo;
            *reinterpret_cast<uint4*>(smem + A_HI + SWZ(bo + 16)) = shi;
            *reinterpret_cast<uint4*>(smem + A_LO + SWZ(bo + 16)) = slo;
        }
        CP_WAIT1();
        __syncthreads();
        const int BM = B_M0 + (c & 1) * 16384;
#pragma unroll
        for (int kk = 0; kk < 4; ++kk) {
            const uint32_t kb = kk * 32;
            uint32_t bm[8][2];
#pragma unroll
            for (int nt = 0; nt < 8; ++nt) {
                uint32_t addr = smem_base + SWZ((uint32_t)((n0 + nt * 8 + (lane & 7)) * 128 + kb + (((lane & 15) >> 3) & 1) * 16));
                LDSM2(bm[nt], addr + BM);
            }
#pragma unroll
            for (int mt = 0; mt < 4; ++mt) {
                uint32_t addr = smem_base + SWZ((uint32_t)((m0 + mt * 16 + (lane & 15)) * 128 + kb + (lane >> 4) * 16));
                uint32_t ah[4], al[4];
                LDSM4(ah, addr + A_HI);
                LDSM4(al, addr + A_LO);
#pragma unroll
                for (int nt = 0; nt < 8; ++nt) MMA_F32(acc[mt][nt], ah, bm[nt]);
#pragma unroll
                for (int nt = 0; nt < 8; ++nt) MMA_F32(acc[mt][nt], al, bm[nt]);
            }
        }
    }

    const int g4 = lane >> 2, t4 = lane & 3;
#pragma unroll
    for (int mt = 0; mt < 4; ++mt) {
        int r0 = row0 + m0 + mt * 16 + g4;
        int r1 = r0 + 8;
        float sc0 = 1.0f, sc1 = 1.0f;
        bool v0 = r0 < NN, v1 = r1 < NN;
        if (out_scale) {
            if (v0) sc0 = out_scale[r0];
            if (v1) sc1 = out_scale[r1];
        }
#pragma unroll
        for (int nt = 0; nt < 8; ++nt) {
            int col = n0 + nt * 8 + t4 * 2;
            if (v0) {
                float2* p = reinterpret_cast<float2*>(out + (size_t)r0 * 128 + col);
                *p = make_float2(acc[mt][nt][0] * sc0, acc[mt][nt][1] * sc0);
            }
            if (v1) {
                float2* p = reinterpret_cast<float2*>(out + (size_t)r1 * 128 + col);
                *p = make_float2(acc[mt][nt][2] * sc1, acc[mt][nt][3] * sc1);
            }
        }
    }
}

// ---------------- CSR aggregation ----------------
__global__ void aggregate(const float* __restrict__ hf,
                          const int* __restrict__ off, const int* __restrict__ srcv,
                          float* __restrict__ out) {
    int warp = (blockIdx.x * blockDim.x + threadIdx.x) >> 5;
    int lane = threadIdx.x & 31;
    if (warp >= NN) return;
    int e  = off[warp];
    int e1 = off[warp + 1];
    float4 a0 = make_float4(0.f, 0.f, 0.f, 0.f);
    float4 a1 = make_float4(0.f, 0.f, 0.f, 0.f);
    for (; e + 1 < e1; e += 2) {
        int r0 = __ldg(&srcv[e]);
        int r1 = __ldg(&srcv[e + 1]);
        float4 v0 = *reinterpret_cast<const float4*>(hf + (size_t)r0 * 128 + lane * 4);
        float4 v1 = *reinterpret_cast<const float4*>(hf + (size_t)r1 * 128 + lane * 4);
        a0.x += v0.x; a0.y += v0.y; a0.z += v0.z; a0.w += v0.w;
        a1.x += v1.x; a1.y += v1.y; a1.z += v1.z; a1.w += v1.w;
    }
    if (e < e1) {
        int r0 = __ldg(&srcv[e]);
        float4 v0 = *reinterpret_cast<const float4*>(hf + (size_t)r0 * 128 + lane * 4);
        a0.x += v0.x; a0.y += v0.y; a0.z += v0.z; a0.w += v0.w;
    }
    a0.x += a1.x; a0.y += a1.y; a0.z += a1.z; a0.w += a1.w;
    *reinterpret_cast<float4*>(out + (size_t)warp * 128 + lane * 4) = a0;
}

// ---------------- pooling ----------------
__global__ void pool_kernel(const float* __restrict__ h, const int* __restrict__ batch,
                            const float* __restrict__ dinv,
                            float* __restrict__ sums, float* __restrict__ cnts) {
    const int PER = 25;
    int warp = (blockIdx.x * blockDim.x + threadIdx.x) >> 5;
    int lane = threadIdx.x & 31;
    int n0 = warp * PER;
    if (n0 >= NN) return;
    int n1 = n0 + PER;
    if (n1 > NN) n1 = NN;
    float4 acc = make_float4(0.f, 0.f, 0.f, 0.f);
    float cnt = 0.f;
    int cg = batch[n0];
    for (int n = n0; n < n1; n++) {
        int g = batch[n];
        if (g != cg) {
            float* p = sums + (size_t)cg * 128 + lane * 4;
            atomicAdd(p + 0, acc.x); atomicAdd(p + 1, acc.y);
            atomicAdd(p + 2, acc.z); atomicAdd(p + 3, acc.w);
            if (lane == 0) atomicAdd(&cnts[cg], cnt);
            acc = make_float4(0.f, 0.f, 0.f, 0.f);
            cnt = 0.f; cg = g;
        }
        float w = dinv[n];
        float4 v = *reinterpret_cast<const float4*>(h + (size_t)n * 128 + lane * 4);
        acc.x += w * v.x; acc.y += w * v.y; acc.z += w * v.z; acc.w += w * v.w;
        cnt += 1.f;
    }
    float* p = sums + (size_t)cg * 128 + lane * 4;
    atomicAdd(p + 0, acc.x); atomicAdd(p + 1, acc.y);
    atomicAdd(p + 2, acc.z); atomicAdd(p + 3, acc.w);
    if (lane == 0) atomicAdd(&cnts[cg], cnt);
}

// ---------------- readout ----------------
__global__ void readout_kernel(const float* __restrict__ sums, const float* __restrict__ cnts,
                               const float* __restrict__ Wt,
                               float* __restrict__ out) {
    __shared__ float phi[2048];
    __shared__ float red[4][32];
    const int g = blockIdx.x;
    const int tid = threadIdx.x;     // 128 threads
    float cnt = fmaxf(cnts[g], 1.0f);
    float x = sums[(size_t)g * 128 + tid] / cnt;
    float cv[8], sv[8];
    phi_expand(x, cv, sv);
#pragma unroll
    for (int h = 0; h < 8; h++) {
        phi[tid * 16 + h]     = cv[h];
        phi[tid * 16 + 8 + h] = sv[h];
    }
    __syncthreads();
    const int o = tid & 31;
    const int part = tid >> 5;
    float acc = 0.f;
    int k0 = part * 512;
#pragma unroll 8
    for (int k = k0; k < k0 + 512; k++) acc += phi[k] * Wt[k * 32 + o];
    red[part][o] = acc;
    __syncthreads();
    if (tid < 32)
        out[(size_t)g * 32 + tid] = red[0][tid] + red[1][tid] + red[2][tid] + red[3][tid];
}

// ---------------- launch ----------------
extern "C" void kernel_launch(void* const* d_in, const int* in_sizes, int n_in,
                              void* d_out, int out_size) {
    const float* features = (const float*)d_in[0];   // [N,64]
    const int*   edges    = (const int*)d_in[1];     // [2,E]
    const int*   batch    = (const int*)d_in[2];     // [N]
    const float* W_embed  = (const float*)d_in[3];   // [2,128,64,8]
    const float* W_mp     = (const float*)d_in[4];   // [3,2,128,128,8]
    const float* W_read   = (const float*)d_in[5];   // [2,32,128,8]
    float* out = (float*)d_out;                      // [64,32]

    float *h0, *h1, *hf, *dinv, *wtr, *sums, *cnts;
    int *deg, *off, *cur, *srcv, *bsum, *boff;
    __half *bhe, *ble, *bhm, *blm;
    cudaGetSymbolAddress((void**)&h0,   g_h0);
    cudaGetSymbolAddress((void**)&h1,   g_h1);
    cudaGetSymbolAddress((void**)&hf,   g_hf);
    cudaGetSymbolAddress((void**)&dinv, g_dinv);
    cudaGetSymbolAddress((void**)&deg,  g_deg);
    cudaGetSymbolAddress((void**)&off,  g_off);
    cudaGetSymbolAddress((void**)&cur,  g_cur);
    cudaGetSymbolAddress((void**)&srcv, g_srcv);
    cudaGetSymbolAddress((void**)&bsum, g_bsum);
    cudaGetSymbolAddress((void**)&boff, g_boff);
    cudaGetSymbolAddress((void**)&bhe,  g_bhe);
    cudaGetSymbolAddress((void**)&ble,  g_ble);
    cudaGetSymbolAddress((void**)&bhm,  g_bhm);
    cudaGetSymbolAddress((void**)&blm,  g_blm);
    cudaGetSymbolAddress((void**)&wtr,  g_wtr);
    cudaGetSymbolAddress((void**)&sums, g_sums);
    cudaGetSymbolAddress((void**)&cnts, g_cnts);

    const int* erow = edges;
    const int* ecol = edges + EE;

    cudaFuncSetAttribute(kan_hmma, cudaFuncAttributeMaxDynamicSharedMemorySize, 98304);
    cudaFuncSetAttribute(kan_hmma16, cudaFuncAttributeMaxDynamicSharedMemorySize, 65536);

    // Host-side stream/events created once (no device memory involved).
    static cudaStream_t s_side = nullptr;
    static cudaEvent_t  s_fork = nullptr, s_join = nullptr;
    if (s_side == nullptr) {
        cudaStreamCreateWithFlags(&s_side, cudaStreamNonBlocking);
        cudaEventCreateWithFlags(&s_fork, cudaEventDisableTiming);
        cudaEventCreateWithFlags(&s_join, cudaEventDisableTiming);
    }

    const int gblocks = (NN + 127) / 128;   // 391
    const int agg_blocks = (NN * 32 + 255) / 256;
    const int nb = (NN + 255) / 256;        // 196

    // [main] weight prep; make_b_embed also zeroes deg/sums/cnts
    make_b_embed<<<(128 * 1024 + 255) / 256, 256>>>(W_embed, bhe, ble, deg, sums, cnts);
    cudaEventRecord(s_fork, 0);             // fork point: deg is zeroed

    make_b_mp<<<(3 * 128 * 2048 + 255) / 256, 256>>>(W_mp, bhm, blm);
    transpose_wr<<<(2048 * 32 + 255) / 256, 256>>>(W_read, wtr);

    // [main] embed: h0 = kan(features)   [my 4th launch — ncu target]
    kan_hmma<<<gblocks, 128, 98304>>>(features, 64, bhe, ble, nullptr, nullptr, h0);
    // [main] mp 0 (fp16 3-term)
    kan_hmma<<<gblocks, 128, 98304>>>(h0, 128, bhm, blm, nullptr, dinv, hf);

    // [side] CSR build, concurrent with embed+mp0 GEMMs
    cudaStreamWaitEvent(s_side, s_fork, 0);
    count_deg<<<(EE + 255) / 256, 256, 0, s_side>>>(ecol, deg);
    deg_bsum<<<nb, 256, 0, s_side>>>(deg, bsum, dinv);
    scan_bsum<<<1, 256, 0, s_side>>>(bsum, boff, nb, off);
    scan_write<<<nb, 256, 0, s_side>>>(deg, boff, off, cur);
    fill_csr<<<(EE + NN + 255) / 256, 256, 0, s_side>>>(erow, ecol, cur, srcv);
    cudaEventRecord(s_join, s_side);

    // [main] join before first aggregate (needs off/srcv; mp1 needs dinv)
    cudaStreamWaitEvent(0, s_join, 0);

    aggregate<<<agg_blocks, 256>>>(hf, off, srcv, h1);
    // mp 1 (fp16 3-term)
    kan_hmma<<<gblocks, 128, 98304>>>(h1, 128, bhm + 128 * 2048, blm + 128 * 2048, dinv, dinv, hf);
    aggregate<<<agg_blocks, 256>>>(hf, off, srcv, h0);
    // mp 2 (fp16 2-term; B = hi plane of layer 2)
    kan_hmma16<<<gblocks, 128, 65536>>>(h0, bhm + 2 * 128 * 2048, dinv, dinv, hf);
    aggregate<<<agg_blocks, 256>>>(hf, off, srcv, h1);

    // pool + readout
    pool_kernel<<<250, 256>>>(h1, batch, dinv, sums, cnts);
    readout_kernel<<<GG, 128>>>(sums, cnts, wtr, out);
}